// round 10
// baseline (speedup 1.0000x reference)
#include <cuda_runtime.h>
#include <cstdint>

// out[o*256+k][h][m] = sum_{i,j} w[i][k][j] * xp[m+j], xp = padded/rolled row.
// Grid 112 = (o:2, kq:4, h:14). Block 512 = 16 warps; warp g owns i in [16g, 16g+16).
// Lane = adjacent channel pair k0 = kq*64 + 2*lane (f32x2 lanes = 2 output chans).
// Weights: verbatim cp.async copy (coalesced float4) of the block's kq-slice,
//   raw layout SR[i][192 floats]; split in 2 halves by (i mod 16) so all warps
//   start after half 1. Mainloop: 3 raw LDS.64 + 3 pk2 + 8 bcast LDS.128 + 42 FFMA2/il.
// x: per-warp duplicated-pair table SX[g][il][a] (u64 {v,v}).
// Deterministic cross-warp smem reduction at the end.

#define W_FLOATS (256 * 192)              // 49152 floats = 192KB raw weights
#define X_U64    (16 * 16 * 16)           // 4096 u64 = 32KB
#define SMEM_BYTES (W_FLOATS * 4 + X_U64 * 8)   // 224KB

extern __shared__ float smem[];

__device__ __forceinline__ uint64_t pkab(float a, float b) {
    uint64_t r;
    asm("mov.b64 %0, {%1, %2};" : "=l"(r)
        : "r"(__float_as_uint(a)), "r"(__float_as_uint(b)));
    return r;
}
__device__ __forceinline__ uint64_t ffma2(uint64_t a, uint64_t b, uint64_t c) {
    uint64_t d;
    asm("fma.rn.f32x2 %0, %1, %2, %3;" : "=l"(d) : "l"(a), "l"(b), "l"(c));
    return d;
}
__device__ __forceinline__ void cp16(uint32_t s, const void* g) {
    asm volatile("cp.async.cg.shared.global [%0], [%1], 16;" :: "r"(s), "l"(g) : "memory");
}
__device__ __forceinline__ void cp_commit() {
    asm volatile("cp.async.commit_group;" ::: "memory");
}
template <int N> __device__ __forceinline__ void cp_wait() {
    asm volatile("cp.async.wait_group %0;" :: "n"(N) : "memory");
}

__global__ __launch_bounds__(512, 1)
void fused_conv_kernel(const float* __restrict__ x,
                       const float* __restrict__ w,
                       float* __restrict__ out) {
    const int bx = blockIdx.x;           // 0..111
    const int o  = bx / 56;
    const int kq = (bx / 14) & 3;
    const int h  = bx % 14;
    const int tid  = threadIdx.x;
    const int g    = tid >> 5;           // warp / i-group 0..15
    const int lane = tid & 31;
    const int n    = (h + 13) % 14;      // undo roll along H
    const int k0   = kq * 64 + 2 * lane;

    float*    swr = smem;                            // SR[i][192]
    uint64_t* sxd = (uint64_t*)(smem + W_FLOATS);    // SX[g][il][a]

    const uint32_t s_u32 = (uint32_t)__cvta_generic_to_shared(smem);
    const float* wb = w + (size_t)kq * 192;

    // ---- cp.async weight copy, 2 halves split by (i mod 16) ----
    // half c, row r (0..127): i = (r>>3)*16 + c*8 + (r&7); 48 f4 per row.
#define ISSUE_HALF(cc)                                                        \
    {                                                                         \
        _Pragma("unroll")                                                     \
        for (int it = 0; it < 12; it++) {                                     \
            const int f4  = it * 512 + tid;         /* 0..6143 */             \
            const int r   = f4 / 48;                                          \
            const int col = f4 % 48;                                          \
            const int i   = (r >> 3) * 16 + (cc) * 8 + (r & 7);               \
            cp16(s_u32 + (uint32_t)(i * 192 + col * 4) * 4,                   \
                 wb + (size_t)i * 768 + col * 4);                             \
        }                                                                     \
        cp_commit();                                                          \
    }
    ISSUE_HALF(0)
    ISSUE_HALF(1)

    // ---- stage x (duplicated pairs), per-warp private ----
    // xp[a] = (a in [1,14]) ? x[(o*256+i)*196 + n*14 + (a+12)%14] : 0
    {
        const float* xb = x + ((size_t)o * 256 + g * 16) * 196 + n * 14;
#pragma unroll
        for (int r = 0; r < 8; r++) {
            const int idx = r * 32 + lane;       // 0..255
            const int il = idx >> 4;
            const int a  = idx & 15;
            float v = 0.f;
            if (a >= 1 && a <= 14) v = xb[(size_t)il * 196 + (a + 12) % 14];
            sxd[g * 256 + idx] = pkab(v, v);
        }
    }

    uint64_t acc[14];
#pragma unroll
    for (int m = 0; m < 14; m++) acc[m] = 0ull;

    // ---- mainloop: 2 halves x 8 il ----
#pragma unroll
    for (int half = 0; half < 2; half++) {
        if (half == 0) cp_wait<1>(); else cp_wait<0>();
        __syncthreads();                 // half's weights + (half 0) x staging visible

#pragma unroll
        for (int q = 0; q < 8; q++) {
            const int il = half * 8 + q;
            const int i  = g * 16 + il;
            // raw 6 floats: [a0 a1 | a2 b0 | b1 b2] for channels (k0, k0+1)
            const float2* wr = (const float2*)(swr + (size_t)i * 192 + lane * 6);
            const float2 A = wr[0];
            const float2 B = wr[1];
            const float2 C = wr[2];
            const uint64_t W0 = pkab(A.x, B.y);
            const uint64_t W1 = pkab(A.y, C.x);
            const uint64_t W2 = pkab(B.x, C.y);

            const ulonglong2* xd = (const ulonglong2*)(sxd + g * 256 + il * 16);
            uint64_t X[16];
#pragma unroll
            for (int t = 0; t < 8; t++) {       // 8 broadcast LDS.128
                const ulonglong2 v = xd[t];
                X[2 * t]     = v.x;
                X[2 * t + 1] = v.y;
            }

#pragma unroll
            for (int m = 0; m < 14; m++) {
                acc[m] = ffma2(W0, X[m],     acc[m]);
                acc[m] = ffma2(W1, X[m + 1], acc[m]);
                acc[m] = ffma2(W2, X[m + 2], acc[m]);
            }
        }
    }

    // ---- cross-warp reduction (reuse weight region) ----
    __syncthreads();                     // everyone done reading SR
    uint64_t* ps = (uint64_t*)smem;      // ps[(g*32+lane)*14 + m], 56KB
#pragma unroll
    for (int m = 0; m < 14; m++)
        ps[((size_t)(g * 32 + lane)) * 14 + m] = acc[m];
    __syncthreads();

    if (tid < 448) {
        const int lk = tid / 14;         // lane-pair 0..31
        const int m  = tid % 14;
        float lo = 0.f, hi = 0.f;
#pragma unroll
        for (int gg = 0; gg < 16; gg++) {    // fixed order -> deterministic
            const float2 v = ((const float2*)ps)[(gg * 32 + lk) * 14 + m];
            lo += v.x;
            hi += v.y;
        }
        const int cg = o * 256 + kq * 64 + 2 * lk;
        out[(size_t)cg * 196 + h * 14 + m]       = lo;
        out[(size_t)(cg + 1) * 196 + h * 14 + m] = hi;
    }
}

extern "C" void kernel_launch(void* const* d_in, const int* in_sizes, int n_in,
                              void* d_out, int out_size) {
    const float* x = (const float*)d_in[0];   // (1,512,14,14)
    const float* w = (const float*)d_in[1];   // (256,256,3)
    float* out = (float*)d_out;

    cudaFuncSetAttribute(fused_conv_kernel,
                         cudaFuncAttributeMaxDynamicSharedMemorySize, SMEM_BYTES);
    fused_conv_kernel<<<112, 512, SMEM_BYTES>>>(x, w, out);
}